// round 7
// baseline (speedup 1.0000x reference)
#include <cuda_runtime.h>

#define BINS    10
#define BLOCK   256
#define MAXGRID 1024

// Per-block partials: every block writes only its own slot -> no init kernel.
__device__ float2       g_part[MAXGRID][BINS];
__device__ unsigned int g_arrive;   // zero at module load; last block resets it

__device__ __forceinline__ void process_elem(float x, float t, float lw,
                                             float2* slot) {
    float u   = __expf(-x);               // FMUL + MUFU.EX2
    float w1  = 1.0f + u;
    float s   = __fdividef(1.0f, w1);     // sigmoid via MUFU.RCP
    float sp  = x + __logf(w1);           // softplus(x) = x + ln(1+e^{-x})
    float g10 = fabsf(s - t) * (float)BINS;
    int bin   = (int)g10;                 // g10 >= 0 -> trunc == floor
    bin = bin > (BINS - 1) ? (BINS - 1) : bin;
    float bce = fmaf(-x, t, sp);          // softplus(x) - x*t
    float2 a  = slot[bin * BLOCK];        // LDS.64
    a.x += lw;                            // lw in {0,1} masks both sums
    a.y += bce * lw;
    slot[bin * BLOCK] = a;                // STS.64
}

__global__ void __launch_bounds__(BLOCK, 5)
ghmc_fused(const float4* __restrict__ pred4,
           const float4* __restrict__ targ4,
           const float4* __restrict__ lw4,
           int nquads, float* __restrict__ out) {
    // Two parity banks of [bin][tid] float2 slots (40 KB): conflict-free
    // (lane==tid at 8B granularity); per-quad RMWs form two independent
    // 2-deep chains. 5 blocks/SM * 40KB = 200KB < 228KB.
    __shared__ float2 s_acc[2][BINS * BLOCK];
    int tid = threadIdx.x;
    #pragma unroll
    for (int b = 0; b < BINS; b++) {
        s_acc[0][b * BLOCK + tid] = make_float2(0.f, 0.f);
        s_acc[1][b * BLOCK + tid] = make_float2(0.f, 0.f);
    }
    __syncthreads();
    float2* slot0 = &s_acc[0][tid];
    float2* slot1 = &s_acc[1][tid];

    int stride = gridDim.x * BLOCK;
    int i = blockIdx.x * BLOCK + tid;

    // Software pipeline: iteration i+1's three LDG.128 issue before iteration
    // i's compute/smem chain (neutral in R6, kept — decouples LDG latency).
    float4 p = make_float4(0.f, 0.f, 0.f, 0.f);
    float4 t = p, w = p;                  // lw=0 defaults: contribute nothing
    if (i < nquads) { p = pred4[i]; t = targ4[i]; w = lw4[i]; }

    #pragma unroll 1
    for (; i < nquads; ) {
        int j = i + stride;
        float4 pn, tn, wn;
        bool more = (j < nquads);
        if (more) { pn = pred4[j]; tn = targ4[j]; wn = lw4[j]; }
        process_elem(p.x, t.x, w.x, slot0);
        process_elem(p.y, t.y, w.y, slot1);
        process_elem(p.z, t.z, w.z, slot0);
        process_elem(p.w, t.w, w.w, slot1);
        if (!more) break;
        p = pn; t = tn; w = wn; i = j;
    }
    __syncthreads();

    // Block tree-reduction; fold parity bank 1 into bank 0 on the first pass.
    if (tid < 128) {
        #pragma unroll
        for (int b = 0; b < BINS; b++) {
            float2 a = s_acc[0][b * BLOCK + tid];
            float2 c = s_acc[0][b * BLOCK + tid + 128];
            float2 d = s_acc[1][b * BLOCK + tid];
            float2 e = s_acc[1][b * BLOCK + tid + 128];
            a.x += c.x + d.x + e.x;
            a.y += c.y + d.y + e.y;
            s_acc[0][b * BLOCK + tid] = a;
        }
    }
    __syncthreads();
    for (int off = 64; off > 0; off >>= 1) {
        if (tid < off) {
            #pragma unroll
            for (int b = 0; b < BINS; b++) {
                float2 a = s_acc[0][b * BLOCK + tid];
                float2 c = s_acc[0][b * BLOCK + tid + off];
                a.x += c.x; a.y += c.y;
                s_acc[0][b * BLOCK + tid] = a;
            }
        }
        __syncthreads();
    }
    if (tid < BINS)
        g_part[blockIdx.x][tid] = s_acc[0][tid * BLOCK];

    // ---- last-block-done finalize (deterministic: counter self-resets) ----
    __shared__ unsigned int s_ticket;
    __threadfence();
    if (tid == 0) s_ticket = atomicAdd(&g_arrive, 1u);
    __syncthreads();
    if (s_ticket != gridDim.x - 1) return;

    __threadfence();  // acquire all blocks' partial writes
    int lane = tid & 31, wid = tid >> 5;
    float2 acc[BINS];
    #pragma unroll
    for (int b = 0; b < BINS; b++) acc[b] = make_float2(0.f, 0.f);
    for (int k = tid; k < (int)gridDim.x; k += BLOCK) {
        #pragma unroll
        for (int b = 0; b < BINS; b++) {
            float2 v = g_part[k][b];
            acc[b].x += v.x; acc[b].y += v.y;
        }
    }
    #pragma unroll
    for (int b = 0; b < BINS; b++) {
        #pragma unroll
        for (int off = 16; off > 0; off >>= 1) {
            acc[b].x += __shfl_down_sync(0xffffffffu, acc[b].x, off);
            acc[b].y += __shfl_down_sync(0xffffffffu, acc[b].y, off);
        }
    }
    __shared__ float2 s_red[BLOCK / 32][BINS];
    if (lane == 0)
        #pragma unroll
        for (int b = 0; b < BINS; b++) s_red[wid][b] = acc[b];
    __syncthreads();
    if (tid == 0) {
        // loss = (1/n) * sum_b S[b]/counts[b]   (tot cancels exactly)
        double loss = 0.0;
        int n = 0;
        #pragma unroll
        for (int b = 0; b < BINS; b++) {
            double c = 0.0, s = 0.0;
            for (int w = 0; w < BLOCK / 32; w++) {
                c += (double)s_red[w][b].x;
                s += (double)s_red[w][b].y;
            }
            if (c > 0.0) { n++; loss += s / c; }
        }
        out[0] = (float)(n > 0 ? loss / (double)n : 0.0);
        g_arrive = 0u;   // pristine state for the next graph replay
    }
}

extern "C" void kernel_launch(void* const* d_in, const int* in_sizes, int n_in,
                              void* d_out, int out_size) {
    const float* pred = (const float*)d_in[0];
    const float* targ = (const float*)d_in[1];
    const float* lw   = (const float*)d_in[2];
    float* out = (float*)d_out;

    int n  = in_sizes[0];
    int nq = n / 4;   // N*C divisible by 4: no scalar tail

    int grid = 740;   // 5 blocks/SM * 148 SMs -> 40 warps/SM, single wave
    int max_grid = (nq + BLOCK - 1) / BLOCK;
    if (max_grid < 1) max_grid = 1;
    if (grid > max_grid) grid = max_grid;

    ghmc_fused<<<grid, BLOCK>>>((const float4*)pred, (const float4*)targ,
                                (const float4*)lw, nq, out);
}

// round 9
// speedup vs baseline: 1.1060x; 1.1060x over previous
#include <cuda_runtime.h>

#define BINS    10
#define BLOCK   256
#define STAGES  4
#define MAXGRID 1024

// Per-block partials: every block writes only its own slot -> no init kernel.
__device__ float2       g_part[MAXGRID][BINS];
__device__ unsigned int g_arrive;   // zero at module load; last block resets it

// Dynamic smem layout:
//   float4 st_p[STAGES*BLOCK]   (16 KB)
//   float4 st_t[STAGES*BLOCK]   (16 KB)
//   float4 st_w[STAGES*BLOCK]   (16 KB)
//   float2 s_acc[2*BINS*BLOCK]  (40 KB)   -> 88 KB total, 2 blocks/SM
#define SMEM_BYTES ((3 * STAGES * BLOCK * 16) + (2 * BINS * BLOCK * 8))

__device__ __forceinline__ void cp16(void* dst_smem, const void* src_gmem) {
    unsigned s = (unsigned)__cvta_generic_to_shared(dst_smem);
    asm volatile("cp.async.cg.shared.global [%0], [%1], 16;\n"
                 :: "r"(s), "l"(src_gmem) : "memory");
}

__device__ __forceinline__ void process_elem(float x, float t, float lw,
                                             float2* slot) {
    float u   = __expf(-x);               // FMUL + MUFU.EX2
    float w1  = 1.0f + u;
    float s   = __fdividef(1.0f, w1);     // sigmoid via MUFU.RCP
    float sp  = x + __logf(w1);           // softplus(x) = x + ln(1+e^{-x})
    float g10 = fabsf(s - t) * (float)BINS;
    int bin   = (int)g10;                 // g10 >= 0 -> trunc == floor
    bin = bin > (BINS - 1) ? (BINS - 1) : bin;
    float bce = fmaf(-x, t, sp);          // softplus(x) - x*t
    float2 a  = slot[bin * BLOCK];        // LDS.64
    a.x += lw;                            // lw in {0,1} masks both sums
    a.y += bce * lw;
    slot[bin * BLOCK] = a;                // STS.64
}

__global__ void __launch_bounds__(BLOCK)
ghmc_fused(const float4* __restrict__ pred4,
           const float4* __restrict__ targ4,
           const float4* __restrict__ lw4,
           int nquads, float* __restrict__ out) {
    extern __shared__ char smem_raw[];
    float4* st_p  = (float4*)smem_raw;
    float4* st_t  = st_p + STAGES * BLOCK;
    float4* st_w  = st_t + STAGES * BLOCK;
    float2* s_acc = (float2*)(st_w + STAGES * BLOCK);

    int tid = threadIdx.x;
    int bid = blockIdx.x;
    int g   = gridDim.x;

    #pragma unroll
    for (int b = 0; b < BINS; b++) {
        s_acc[b * BLOCK + tid]                = make_float2(0.f, 0.f);
        s_acc[BINS * BLOCK + b * BLOCK + tid] = make_float2(0.f, 0.f);
    }
    __syncthreads();
    float2* slot0 = &s_acc[tid];
    float2* slot1 = &s_acc[BINS * BLOCK + tid];

    // Tiles of BLOCK quads; this block owns tiles bid, bid+g, bid+2g, ...
    int NT   = (nquads + BLOCK - 1) / BLOCK;
    int nt_b = (bid < NT) ? (NT - bid + g - 1) / g : 0;

    // ---- cp.async pipeline prologue: stages 0..S-2 ----
    #pragma unroll
    for (int s = 0; s < STAGES - 1; s++) {
        if (s < nt_b) {
            int gq = (bid + s * g) * BLOCK + tid;
            if (gq < nquads) {
                cp16(&st_p[s * BLOCK + tid], pred4 + gq);
                cp16(&st_t[s * BLOCK + tid], targ4 + gq);
                cp16(&st_w[s * BLOCK + tid], lw4   + gq);
            }
        }
        asm volatile("cp.async.commit_group;" ::: "memory");
    }

    // ---- main pipelined loop ----
    for (int k = 0; k < nt_b; k++) {
        // tile k's group complete when <= S-2 groups pending
        asm volatile("cp.async.wait_group 2;" ::: "memory");
        __syncthreads();   // data visible to all; tile k-1 fully consumed

        // issue tile k+S-1 into buffer (k+S-1)%S (== (k-1)%S, consumed at k-1)
        int kf = k + STAGES - 1;
        if (kf < nt_b) {
            int bufF = kf % STAGES;
            int gq = (bid + kf * g) * BLOCK + tid;
            if (gq < nquads) {
                cp16(&st_p[bufF * BLOCK + tid], pred4 + gq);
                cp16(&st_t[bufF * BLOCK + tid], targ4 + gq);
                cp16(&st_w[bufF * BLOCK + tid], lw4   + gq);
            }
        }
        asm volatile("cp.async.commit_group;" ::: "memory");

        // process tile k from buffer k%S
        int buf = k % STAGES;
        int gq = (bid + k * g) * BLOCK + tid;
        if (gq < nquads) {
            float4 p = st_p[buf * BLOCK + tid];
            float4 t = st_t[buf * BLOCK + tid];
            float4 w = st_w[buf * BLOCK + tid];
            process_elem(p.x, t.x, w.x, slot0);
            process_elem(p.y, t.y, w.y, slot1);
            process_elem(p.z, t.z, w.z, slot0);
            process_elem(p.w, t.w, w.w, slot1);
        }
    }
    __syncthreads();

    // Block tree-reduction; fold parity bank 1 into bank 0 on the first pass.
    if (tid < 128) {
        #pragma unroll
        for (int b = 0; b < BINS; b++) {
            float2 a = s_acc[b * BLOCK + tid];
            float2 c = s_acc[b * BLOCK + tid + 128];
            float2 d = s_acc[BINS * BLOCK + b * BLOCK + tid];
            float2 e = s_acc[BINS * BLOCK + b * BLOCK + tid + 128];
            a.x += c.x + d.x + e.x;
            a.y += c.y + d.y + e.y;
            s_acc[b * BLOCK + tid] = a;
        }
    }
    __syncthreads();
    for (int off = 64; off > 0; off >>= 1) {
        if (tid < off) {
            #pragma unroll
            for (int b = 0; b < BINS; b++) {
                float2 a = s_acc[b * BLOCK + tid];
                float2 c = s_acc[b * BLOCK + tid + off];
                a.x += c.x; a.y += c.y;
                s_acc[b * BLOCK + tid] = a;
            }
        }
        __syncthreads();
    }
    if (tid < BINS)
        g_part[bid][tid] = s_acc[tid * BLOCK];

    // ---- last-block-done finalize (deterministic: counter self-resets) ----
    __shared__ unsigned int s_ticket;
    __threadfence();
    if (tid == 0) s_ticket = atomicAdd(&g_arrive, 1u);
    __syncthreads();
    if (s_ticket != gridDim.x - 1) return;

    __threadfence();  // acquire all blocks' partial writes
    int lane = tid & 31, wid = tid >> 5;
    float2 acc[BINS];
    #pragma unroll
    for (int b = 0; b < BINS; b++) acc[b] = make_float2(0.f, 0.f);
    for (int k = tid; k < (int)gridDim.x; k += BLOCK) {
        #pragma unroll
        for (int b = 0; b < BINS; b++) {
            float2 v = g_part[k][b];
            acc[b].x += v.x; acc[b].y += v.y;
        }
    }
    #pragma unroll
    for (int b = 0; b < BINS; b++) {
        #pragma unroll
        for (int off = 16; off > 0; off >>= 1) {
            acc[b].x += __shfl_down_sync(0xffffffffu, acc[b].x, off);
            acc[b].y += __shfl_down_sync(0xffffffffu, acc[b].y, off);
        }
    }
    __shared__ float2 s_red[BLOCK / 32][BINS];
    if (lane == 0)
        #pragma unroll
        for (int b = 0; b < BINS; b++) s_red[wid][b] = acc[b];
    __syncthreads();
    if (tid == 0) {
        // loss = (1/n) * sum_b S[b]/counts[b]   (tot cancels exactly)
        double loss = 0.0;
        int n = 0;
        #pragma unroll
        for (int b = 0; b < BINS; b++) {
            double c = 0.0, s = 0.0;
            for (int w = 0; w < BLOCK / 32; w++) {
                c += (double)s_red[w][b].x;
                s += (double)s_red[w][b].y;
            }
            if (c > 0.0) { n++; loss += s / c; }
        }
        out[0] = (float)(n > 0 ? loss / (double)n : 0.0);
        g_arrive = 0u;   // pristine state for the next graph replay
    }
}

extern "C" void kernel_launch(void* const* d_in, const int* in_sizes, int n_in,
                              void* d_out, int out_size) {
    const float* pred = (const float*)d_in[0];
    const float* targ = (const float*)d_in[1];
    const float* lw   = (const float*)d_in[2];
    float* out = (float*)d_out;

    int n  = in_sizes[0];
    int nq = n / 4;   // N*C divisible by 4: no scalar tail

    static int attr_done = 0;
    if (!attr_done) {
        cudaFuncSetAttribute(ghmc_fused,
                             cudaFuncAttributeMaxDynamicSharedMemorySize,
                             SMEM_BYTES);
        attr_done = 1;
    }

    int grid = 296;   // 2 blocks/SM * 148 SMs (88 KB dynamic smem each)
    int max_grid = (nq + BLOCK - 1) / BLOCK;
    if (max_grid < 1) max_grid = 1;
    if (grid > max_grid) grid = max_grid;

    ghmc_fused<<<grid, BLOCK, SMEM_BYTES>>>((const float4*)pred,
                                            (const float4*)targ,
                                            (const float4*)lw, nq, out);
}

// round 10
// speedup vs baseline: 1.1374x; 1.0283x over previous
#include <cuda_runtime.h>
#include <cstdint>

#define BINS    10
#define BLOCK   256
#define STAGES  5
#define TILE_Q  256                        // quads per tile per array
#define TILE_B  (TILE_Q * 16)              // 4 KB per array per stage
#define MAXGRID 1024

// Per-block partials: every block writes only its own slot -> no init kernel.
__device__ float2       g_part[MAXGRID][BINS];
__device__ unsigned int g_arrive;   // zero at module load; last block resets it

// Dynamic smem: staging ring then histogram banks.
//   float4 stage[STAGES][3][TILE_Q]            (60 KB)
//   float2 s_acc[2][BINS*BLOCK]                (40 KB)   -> 100 KB, 2 blocks/SM
#define SMEM_BYTES ((STAGES * 3 * TILE_B) + (2 * BINS * BLOCK * 8))

__device__ __forceinline__ unsigned smem_u32(const void* p) {
    return (unsigned)__cvta_generic_to_shared(p);
}
__device__ __forceinline__ void mbar_init(unsigned mbar, unsigned count) {
    asm volatile("mbarrier.init.shared.b64 [%0], %1;" :: "r"(mbar), "r"(count) : "memory");
}
__device__ __forceinline__ void mbar_expect_tx(unsigned mbar, unsigned bytes) {
    asm volatile("mbarrier.arrive.expect_tx.shared.b64 _, [%0], %1;"
                 :: "r"(mbar), "r"(bytes) : "memory");
}
__device__ __forceinline__ void mbar_wait(unsigned mbar, unsigned phase) {
    asm volatile(
        "{\n\t"
        ".reg .pred P;\n\t"
        "WAIT_%=:\n\t"
        "mbarrier.try_wait.parity.acquire.cta.shared::cta.b64 P, [%0], %1, 0x989680;\n\t"
        "@P bra.uni DONE_%=;\n\t"
        "bra.uni WAIT_%=;\n\t"
        "DONE_%=:\n\t"
        "}" :: "r"(mbar), "r"(phase) : "memory");
}
// 1D TMA bulk copy global -> shared (SASS: UBLKCP). No tensor map needed.
__device__ __forceinline__ void bulk_g2s(unsigned dst, const void* src,
                                         unsigned bytes, unsigned mbar) {
    asm volatile(
        "cp.async.bulk.shared::cluster.global.mbarrier::complete_tx::bytes "
        "[%0], [%1], %2, [%3];"
        :: "r"(dst), "l"(src), "r"(bytes), "r"(mbar) : "memory");
}

__device__ __forceinline__ void process_elem(float x, float t, float lw,
                                             float2* slot) {
    float u   = __expf(-x);               // FMUL + MUFU.EX2
    float w1  = 1.0f + u;
    float s   = __fdividef(1.0f, w1);     // sigmoid via MUFU.RCP
    float sp  = x + __logf(w1);           // softplus(x) = x + ln(1+e^{-x})
    float g10 = fabsf(s - t) * (float)BINS;
    int bin   = (int)g10;                 // g10 >= 0 -> trunc == floor
    bin = bin > (BINS - 1) ? (BINS - 1) : bin;
    float bce = fmaf(-x, t, sp);          // softplus(x) - x*t
    float2 a  = slot[bin * BLOCK];        // LDS.64
    a.x += lw;                            // lw in {0,1} masks both sums
    a.y += bce * lw;
    slot[bin * BLOCK] = a;                // STS.64
}

__global__ void __launch_bounds__(BLOCK)
ghmc_fused(const float4* __restrict__ pred4,
           const float4* __restrict__ targ4,
           const float4* __restrict__ lw4,
           int nquads, float* __restrict__ out) {
    extern __shared__ char smem_raw[];
    float4* stage = (float4*)smem_raw;                    // [STAGES][3][TILE_Q]
    float2* s_acc = (float2*)(smem_raw + STAGES * 3 * TILE_B);
    __shared__ uint64_t mbar_full[STAGES];

    int tid = threadIdx.x;
    int bid = blockIdx.x;
    int g   = gridDim.x;

    #pragma unroll
    for (int b = 0; b < BINS; b++) {
        s_acc[b * BLOCK + tid]                = make_float2(0.f, 0.f);
        s_acc[BINS * BLOCK + b * BLOCK + tid] = make_float2(0.f, 0.f);
    }
    float2* slot0 = &s_acc[tid];
    float2* slot1 = &s_acc[BINS * BLOCK + tid];

    // Tiles of TILE_Q quads; this block owns tiles bid, bid+g, bid+2g, ...
    int NT   = (nquads + TILE_Q - 1) / TILE_Q;
    int nt_b = (bid < NT) ? (NT - bid + g - 1) / g : 0;

    if (tid == 0) {
        #pragma unroll
        for (int s = 0; s < STAGES; s++)
            mbar_init(smem_u32(&mbar_full[s]), 1u);
    }
    __syncthreads();   // barriers + zeroed histogram visible block-wide

    // ---- prologue: fill all STAGES buffers (tiles 0..S-1 of this block) ----
    if (tid == 0) {
        #pragma unroll
        for (int s = 0; s < STAGES; s++) {
            if (s < nt_b) {
                int  tile  = bid + s * g;
                int  q0    = tile * TILE_Q;
                int  qc    = nquads - q0; if (qc > TILE_Q) qc = TILE_Q;
                unsigned bytes = (unsigned)qc * 16u;
                unsigned mb    = smem_u32(&mbar_full[s]);
                unsigned dst   = smem_u32(stage + (s * 3) * TILE_Q);
                mbar_expect_tx(mb, 3u * bytes);
                bulk_g2s(dst,              pred4 + q0, bytes, mb);
                bulk_g2s(dst + TILE_B,     targ4 + q0, bytes, mb);
                bulk_g2s(dst + 2 * TILE_B, lw4   + q0, bytes, mb);
            }
        }
    }

    // ---- main loop: wait tile k, process, then refill buffer k%S with k+S ----
    for (int k = 0; k < nt_b; k++) {
        int buf   = k % STAGES;
        unsigned mb = smem_u32(&mbar_full[buf]);
        mbar_wait(mb, (unsigned)((k / STAGES) & 1));

        int q0 = (bid + k * g) * TILE_Q;
        int qc = nquads - q0; if (qc > TILE_Q) qc = TILE_Q;
        if (tid < qc) {
            const float4* sp = stage + (buf * 3) * TILE_Q;
            float4 p = sp[tid];
            float4 t = sp[TILE_Q + tid];
            float4 w = sp[2 * TILE_Q + tid];
            process_elem(p.x, t.x, w.x, slot0);
            process_elem(p.y, t.y, w.y, slot1);
            process_elem(p.z, t.z, w.z, slot0);
            process_elem(p.w, t.w, w.w, slot1);
        }
        __syncthreads();   // whole block done with buffer k%S

        int kf = k + STAGES;
        if (tid == 0 && kf < nt_b) {
            int  tile  = bid + kf * g;
            int  fq0   = tile * TILE_Q;
            int  fqc   = nquads - fq0; if (fqc > TILE_Q) fqc = TILE_Q;
            unsigned bytes = (unsigned)fqc * 16u;
            unsigned dst   = smem_u32(stage + (buf * 3) * TILE_Q);
            mbar_expect_tx(mb, 3u * bytes);
            bulk_g2s(dst,              pred4 + fq0, bytes, mb);
            bulk_g2s(dst + TILE_B,     targ4 + fq0, bytes, mb);
            bulk_g2s(dst + 2 * TILE_B, lw4   + fq0, bytes, mb);
        }
    }
    __syncthreads();

    // Block tree-reduction; fold parity bank 1 into bank 0 on the first pass.
    if (tid < 128) {
        #pragma unroll
        for (int b = 0; b < BINS; b++) {
            float2 a = s_acc[b * BLOCK + tid];
            float2 c = s_acc[b * BLOCK + tid + 128];
            float2 d = s_acc[BINS * BLOCK + b * BLOCK + tid];
            float2 e = s_acc[BINS * BLOCK + b * BLOCK + tid + 128];
            a.x += c.x + d.x + e.x;
            a.y += c.y + d.y + e.y;
            s_acc[b * BLOCK + tid] = a;
        }
    }
    __syncthreads();
    for (int off = 64; off > 0; off >>= 1) {
        if (tid < off) {
            #pragma unroll
            for (int b = 0; b < BINS; b++) {
                float2 a = s_acc[b * BLOCK + tid];
                float2 c = s_acc[b * BLOCK + tid + off];
                a.x += c.x; a.y += c.y;
                s_acc[b * BLOCK + tid] = a;
            }
        }
        __syncthreads();
    }
    if (tid < BINS)
        g_part[bid][tid] = s_acc[tid * BLOCK];

    // ---- last-block-done finalize (deterministic: counter self-resets) ----
    __shared__ unsigned int s_ticket;
    __threadfence();
    if (tid == 0) s_ticket = atomicAdd(&g_arrive, 1u);
    __syncthreads();
    if (s_ticket != gridDim.x - 1) return;

    __threadfence();  // acquire all blocks' partial writes
    int lane = tid & 31, wid = tid >> 5;
    float2 acc[BINS];
    #pragma unroll
    for (int b = 0; b < BINS; b++) acc[b] = make_float2(0.f, 0.f);
    for (int k = tid; k < (int)gridDim.x; k += BLOCK) {
        #pragma unroll
        for (int b = 0; b < BINS; b++) {
            float2 v = g_part[k][b];
            acc[b].x += v.x; acc[b].y += v.y;
        }
    }
    #pragma unroll
    for (int b = 0; b < BINS; b++) {
        #pragma unroll
        for (int off = 16; off > 0; off >>= 1) {
            acc[b].x += __shfl_down_sync(0xffffffffu, acc[b].x, off);
            acc[b].y += __shfl_down_sync(0xffffffffu, acc[b].y, off);
        }
    }
    __shared__ float2 s_red[BLOCK / 32][BINS];
    if (lane == 0)
        #pragma unroll
        for (int b = 0; b < BINS; b++) s_red[wid][b] = acc[b];
    __syncthreads();
    if (tid == 0) {
        // loss = (1/n) * sum_b S[b]/counts[b]   (tot cancels exactly)
        double loss = 0.0;
        int n = 0;
        #pragma unroll
        for (int b = 0; b < BINS; b++) {
            double c = 0.0, s = 0.0;
            for (int w = 0; w < BLOCK / 32; w++) {
                c += (double)s_red[w][b].x;
                s += (double)s_red[w][b].y;
            }
            if (c > 0.0) { n++; loss += s / c; }
        }
        out[0] = (float)(n > 0 ? loss / (double)n : 0.0);
        g_arrive = 0u;   // pristine state for the next graph replay
    }
}

extern "C" void kernel_launch(void* const* d_in, const int* in_sizes, int n_in,
                              void* d_out, int out_size) {
    const float* pred = (const float*)d_in[0];
    const float* targ = (const float*)d_in[1];
    const float* lw   = (const float*)d_in[2];
    float* out = (float*)d_out;

    int n  = in_sizes[0];
    int nq = n / 4;   // N*C divisible by 4: no scalar tail

    static int attr_done = 0;
    if (!attr_done) {
        cudaFuncSetAttribute(ghmc_fused,
                             cudaFuncAttributeMaxDynamicSharedMemorySize,
                             SMEM_BYTES);
        attr_done = 1;
    }

    int grid = 296;   // 2 blocks/SM * 148 SMs (100 KB dynamic smem each)
    int max_grid = (nq + TILE_Q - 1) / TILE_Q;
    if (max_grid < 1) max_grid = 1;
    if (grid > max_grid) grid = max_grid;

    ghmc_fused<<<grid, BLOCK, SMEM_BYTES>>>((const float4*)pred,
                                            (const float4*)targ,
                                            (const float4*)lw, nq, out);
}